// round 5
// baseline (speedup 1.0000x reference)
#include <cuda_runtime.h>

#define NQ       12
#define DIM      4096            // 2^12
#define NLAYERS  6
#define NGATES   (NLAYERS * NQ)  // 72
#define THREADS  128
#define APT      (DIM / THREADS) // 32 amplitudes per thread

__device__ __forceinline__ float2 cmul(float2 a, float2 b) {
    return make_float2(fmaf(a.x, b.x, -a.y * b.y),
                       fmaf(a.x, b.y,  a.y * b.x));
}
__device__ __forceinline__ float2 cfma(float2 a, float2 b, float2 c) {
    // a*b + c
    return make_float2(fmaf(a.x, b.x, fmaf(-a.y, b.y, c.x)),
                       fmaf(a.x, b.y, fmaf( a.y, b.x, c.y)));
}

__global__ __launch_bounds__(THREADS, 5)
void qsim_kernel(const float* __restrict__ x,
                 const float* __restrict__ params,
                 float* __restrict__ out) {
    __shared__ float2 sAmp[DIM];          // 32 KB statevector (physical layout)
    __shared__ float2 sGate[NGATES * 4];  // 72 Rot gates (2x2 complex)
    __shared__ float  sc[NQ], ssn[NQ];    // cos(x/2), sin(x/2)
    __shared__ float2 sL[32];             // product table, qubits 7..11
    __shared__ float  sExp[NQ];           // <Z_q> accumulators
    __shared__ unsigned sRowA[NQ];        // rows of A = T^l   (logical bit j at phys p)
    __shared__ unsigned sColB[NQ];        // cols of B = T^-l  (pair masks)

    const int tid = threadIdx.x;
    const int b   = blockIdx.x;

    // ---- stage 0: trig, gate matrices, GF(2) matrices, accumulators ----
    if (tid < NQ) {
        float xv = x[b * NQ + tid];
        sc[tid]    = cosf(0.5f * xv);
        ssn[tid]   = sinf(0.5f * xv);
        sExp[tid]  = 0.0f;
        sRowA[tid] = 1u << tid;   // A = I
        sColB[tid] = 1u << tid;   // B = I
    }
    if (tid < NGATES) {
        float phi = params[tid * 3 + 0];
        float th  = params[tid * 3 + 1];
        float om  = params[tid * 3 + 2];
        float ct = cosf(0.5f * th), st = sinf(0.5f * th);
        float aa = 0.5f * (phi + om), bb = 0.5f * (phi - om);
        float ca = cosf(aa), sa = sinf(aa);
        float cb = cosf(bb), sb = sinf(bb);
        // Rot = [[ep*ct, -em*st], [conj(em)*st, conj(ep)*ct]]
        sGate[tid * 4 + 0] = make_float2( ca * ct, -sa * ct);
        sGate[tid * 4 + 1] = make_float2(-cb * st, -sb * st);
        sGate[tid * 4 + 2] = make_float2( cb * st, -sb * st);
        sGate[tid * 4 + 3] = make_float2( ca * ct,  sa * ct);
    }
    __syncthreads();

    // ---- stage 1: low-5-bit product table (qubits 7..11 <-> bits 4..0) ----
    if (tid < 32) {
        float2 v = make_float2(1.0f, 0.0f);
        #pragma unroll
        for (int j = 0; j < 5; j++) {
            int q   = 7 + j;
            int bit = (tid >> (4 - j)) & 1;
            v = bit ? make_float2(v.y * ssn[q], -v.x * ssn[q])  // v * (-i sin)
                    : make_float2(v.x * sc[q],   v.y * sc[q]);  // v * cos
        }
        sL[tid] = v;
    }
    __syncthreads();

    // ---- stage 2: direct product-state init (RX embedding on |0..0>) ----
    {
        float2 h = make_float2(1.0f, 0.0f);
        #pragma unroll
        for (int j = 0; j < 7; j++) {
            int bit = (tid >> (6 - j)) & 1;
            h = bit ? make_float2(h.y * ssn[j], -h.x * ssn[j])
                    : make_float2(h.x * sc[j],   h.y * sc[j]);
        }
        #pragma unroll
        for (int lo = 0; lo < 32; lo++)
            sAmp[tid * APT + lo] = cmul(h, sL[lo]);
    }
    __syncthreads();

    // ---- stage 3: variational layers; 4 gates fused per pass ----
    // Invariant entering layer l: sPhys[p] = sLogical[A p], A = T^l, B = A^-1.
    for (int l = 0; l < NLAYERS; l++) {
        for (int qp = 0; qp < NQ; qp += 4) {
            const int jA = 11 - qp;
            const unsigned mA = sColB[jA],     mB = sColB[jA - 1];
            const unsigned mC = sColB[jA - 2], mD = sColB[jA - 3];
            const unsigned rA = sRowA[jA],     rB = sRowA[jA - 1];
            const unsigned rC = sRowA[jA - 2], rD = sRowA[jA - 3];

            // Gaussian reduction -> 4 distinct pivot bits
            unsigned w0 = mA;
            int q0 = 31 - __clz((int)w0);
            unsigned w1 = mB;
            if ((w1 >> q0) & 1u) w1 ^= w0;
            int q1 = 31 - __clz((int)w1);
            unsigned w2 = mC;
            if ((w2 >> q0) & 1u) w2 ^= w0;
            if ((w2 >> q1) & 1u) w2 ^= w1;
            int q2 = 31 - __clz((int)w2);
            unsigned w3 = mD;
            if ((w3 >> q0) & 1u) w3 ^= w0;
            if ((w3 >> q1) & 1u) w3 ^= w1;
            if ((w3 >> q2) & 1u) w3 ^= w2;
            int q3 = 31 - __clz((int)w3);
            // sort pivots ascending (5-comparator network)
            int t;
            if (q0 > q1) { t = q0; q0 = q1; q1 = t; }
            if (q2 > q3) { t = q2; q2 = q3; q3 = t; }
            if (q0 > q2) { t = q0; q0 = q2; q2 = t; }
            if (q1 > q3) { t = q1; q1 = q3; q3 = t; }
            if (q1 > q2) { t = q1; q1 = q2; q2 = t; }
            const unsigned m0 = (1u << q0) - 1u, m1 = (1u << q1) - 1u;
            const unsigned m2 = (1u << q2) - 1u, m3 = (1u << q3) - 1u;

            const int gi = (l * NQ + qp) * 4;

            #pragma unroll
            for (int it = 0; it < DIM / 16 / THREADS; it++) {  // 2 groups/thread
                unsigned g = tid + it * THREADS;               // 8-bit coset id
                // insert zero bits at sorted pivot positions
                unsigned rep = ((g   >> q0) << (q0 + 1)) | (g   & m0);
                rep = ((rep >> q1) << (q1 + 1)) | (rep & m1);
                rep = ((rep >> q2) << (q2 + 1)) | (rep & m2);
                rep = ((rep >> q3) << (q3 + 1)) | (rep & m3);
                // canonicalize: logical bits jA..jD of r0 -> 0 (independent: r_j.m_k = delta)
                unsigned r0 = rep;
                if (__popc(rA & rep) & 1) r0 ^= mA;
                if (__popc(rB & rep) & 1) r0 ^= mB;
                if (__popc(rC & rep) & 1) r0 ^= mC;
                if (__popc(rD & rep) & 1) r0 ^= mD;

                float2 v[16];
                #pragma unroll
                for (int k = 0; k < 16; k++) {
                    unsigned off = ((k & 8) ? mA : 0u) ^ ((k & 4) ? mB : 0u)
                                 ^ ((k & 2) ? mC : 0u) ^ ((k & 1) ? mD : 0u);
                    v[k] = sAmp[r0 ^ off];
                }
                {   // gate A (logical bit jA = group bit 3)
                    const float2 G00 = sGate[gi + 0], G01 = sGate[gi + 1];
                    const float2 G10 = sGate[gi + 2], G11 = sGate[gi + 3];
                    #pragma unroll
                    for (int k = 0; k < 8; k++) {
                        float2 v0 = v[k], v1 = v[k + 8];
                        v[k]     = cfma(G00, v0, cmul(G01, v1));
                        v[k + 8] = cfma(G10, v0, cmul(G11, v1));
                    }
                }
                {   // gate B (group bit 2)
                    const float2 G00 = sGate[gi + 4], G01 = sGate[gi + 5];
                    const float2 G10 = sGate[gi + 6], G11 = sGate[gi + 7];
                    #pragma unroll
                    for (int h = 0; h < 16; h += 8)
                        #pragma unroll
                        for (int k = 0; k < 4; k++) {
                            float2 v0 = v[h + k], v1 = v[h + k + 4];
                            v[h + k]     = cfma(G00, v0, cmul(G01, v1));
                            v[h + k + 4] = cfma(G10, v0, cmul(G11, v1));
                        }
                }
                {   // gate C (group bit 1)
                    const float2 G00 = sGate[gi + 8],  G01 = sGate[gi + 9];
                    const float2 G10 = sGate[gi + 10], G11 = sGate[gi + 11];
                    #pragma unroll
                    for (int h = 0; h < 16; h += 4)
                        #pragma unroll
                        for (int k = 0; k < 2; k++) {
                            float2 v0 = v[h + k], v1 = v[h + k + 2];
                            v[h + k]     = cfma(G00, v0, cmul(G01, v1));
                            v[h + k + 2] = cfma(G10, v0, cmul(G11, v1));
                        }
                }
                {   // gate D (group bit 0)
                    const float2 G00 = sGate[gi + 12], G01 = sGate[gi + 13];
                    const float2 G10 = sGate[gi + 14], G11 = sGate[gi + 15];
                    #pragma unroll
                    for (int k = 0; k < 16; k += 2) {
                        float2 v0 = v[k], v1 = v[k + 1];
                        v[k]     = cfma(G00, v0, cmul(G01, v1));
                        v[k + 1] = cfma(G10, v0, cmul(G11, v1));
                    }
                }
                #pragma unroll
                for (int k = 0; k < 16; k++) {
                    unsigned off = ((k & 8) ? mA : 0u) ^ ((k & 4) ? mB : 0u)
                                 ^ ((k & 2) ? mC : 0u) ^ ((k & 1) ? mD : 0u);
                    sAmp[r0 ^ off] = v[k];
                }
            }
            __syncthreads();
        }
        // CNOT chain as matrix update:  A <- T*A ;  B <- B*T^-1
        if (tid == 0) {
            unsigned acc = 0;
            #pragma unroll
            for (int j = NQ - 1; j >= 0; j--) { acc ^= sRowA[j]; sRowA[j] = acc; }
            #pragma unroll
            for (int q = NQ - 1; q >= 1; q--) sColB[q] ^= sColB[q - 1];
        }
        __syncthreads();
    }

    // ---- stage 4: probabilities -> <Z_q> with permuted sign masks ----
    unsigned rq[NQ];
    #pragma unroll
    for (int q = 0; q < NQ; q++) rq[q] = sRowA[11 - q];

    float e[NQ];
    #pragma unroll
    for (int q = 0; q < NQ; q++) e[q] = 0.0f;

    #pragma unroll
    for (int lo = 0; lo < APT; lo++) {
        unsigned p = tid * APT + lo;
        float2 a = sAmp[p];
        float pr = fmaf(a.x, a.x, a.y * a.y);
        #pragma unroll
        for (int q = 0; q < NQ; q++)
            e[q] += (__popc(rq[q] & p) & 1) ? -pr : pr;
    }

    #pragma unroll
    for (int q = 0; q < NQ; q++) {
        float v = e[q];
        #pragma unroll
        for (int off = 16; off > 0; off >>= 1)
            v += __shfl_down_sync(0xffffffffu, v, off);
        if ((tid & 31) == 0) atomicAdd(&sExp[q], v);
    }
    __syncthreads();

    // ---- stage 5: readout mitigation, closed form ----
    // M = J - I => M^-1 = J/(n-1) - I ; out_q = (E+12)/11 - e_q - 2
    if (tid < NQ) {
        float E = 0.0f;
        #pragma unroll
        for (int q = 0; q < NQ; q++) E += sExp[q];
        out[b * NQ + tid] = (E + 12.0f) * (1.0f / 11.0f) - sExp[tid] - 2.0f;
    }
}

extern "C" void kernel_launch(void* const* d_in, const int* in_sizes, int n_in,
                              void* d_out, int out_size) {
    const float* x      = (const float*)d_in[0];
    const float* params = (const float*)d_in[1];
    if (n_in >= 2 && in_sizes[0] == NLAYERS * NQ * 3) {
        x      = (const float*)d_in[1];
        params = (const float*)d_in[0];
    }
    cudaFuncSetAttribute(qsim_kernel,
                         cudaFuncAttributePreferredSharedMemoryCarveout, 100);
    int nblk = out_size / NQ;   // 768
    qsim_kernel<<<nblk, THREADS>>>(x, params, (float*)d_out);
}

// round 6
// speedup vs baseline: 1.0159x; 1.0159x over previous
#include <cuda_runtime.h>

#define NQ       12
#define DIM      4096            // 2^12
#define NLAYERS  6
#define NGATES   (NLAYERS * NQ)  // 72
#define THREADS  128
#define APT      (DIM / THREADS) // 32 amplitudes per thread

// Bank-conflict-avoiding layout: amplitude p lives at sAmp[SWZ(p)].
// GF(2)-linear and invertible: SWZ(a^b) = SWZ(a)^SWZ(b).
#define SWZ(p) ((p) ^ (((p) >> 4) & 0xFu))

__device__ __forceinline__ float2 cmul(float2 a, float2 b) {
    return make_float2(fmaf(a.x, b.x, -a.y * b.y),
                       fmaf(a.x, b.y,  a.y * b.x));
}
__device__ __forceinline__ float2 cfma(float2 a, float2 b, float2 c) {
    // a*b + c
    return make_float2(fmaf(a.x, b.x, fmaf(-a.y, b.y, c.x)),
                       fmaf(a.x, b.y, fmaf( a.y, b.x, c.y)));
}

__global__ __launch_bounds__(THREADS, 6)
void qsim_kernel(const float* __restrict__ x,
                 const float* __restrict__ params,
                 float* __restrict__ out) {
    __shared__ float2 sAmp[DIM];          // 32 KB statevector (swizzled physical layout)
    __shared__ float2 sGate[NGATES * 4];  // 72 Rot gates (2x2 complex)
    __shared__ float  sc[NQ], ssn[NQ];    // cos(x/2), sin(x/2)
    __shared__ float2 sL[32];             // product table, qubits 7..11
    __shared__ float  sExp[NQ];           // <Z_q> accumulators
    __shared__ unsigned sRowA[NQ];        // rows of A = T^l  (logical bit j at phys p)
    __shared__ unsigned sColB[NQ];        // cols of B = T^-l (pair masks)

    const int tid = threadIdx.x;
    const int b   = blockIdx.x;

    // ---- stage 0: trig, gate matrices, GF(2) matrices, accumulators ----
    if (tid < NQ) {
        float xv = x[b * NQ + tid];
        sc[tid]    = cosf(0.5f * xv);
        ssn[tid]   = sinf(0.5f * xv);
        sExp[tid]  = 0.0f;
        sRowA[tid] = 1u << tid;   // A = I
        sColB[tid] = 1u << tid;   // B = I
    }
    if (tid < NGATES) {
        float phi = params[tid * 3 + 0];
        float th  = params[tid * 3 + 1];
        float om  = params[tid * 3 + 2];
        float ct = cosf(0.5f * th), st = sinf(0.5f * th);
        float aa = 0.5f * (phi + om), bb = 0.5f * (phi - om);
        float ca = cosf(aa), sa = sinf(aa);
        float cb = cosf(bb), sb = sinf(bb);
        // Rot = [[ep*ct, -em*st], [conj(em)*st, conj(ep)*ct]]
        sGate[tid * 4 + 0] = make_float2( ca * ct, -sa * ct);
        sGate[tid * 4 + 1] = make_float2(-cb * st, -sb * st);
        sGate[tid * 4 + 2] = make_float2( cb * st, -sb * st);
        sGate[tid * 4 + 3] = make_float2( ca * ct,  sa * ct);
    }
    __syncthreads();

    // ---- stage 1: low-5-bit product table (qubits 7..11 <-> bits 4..0) ----
    if (tid < 32) {
        float2 v = make_float2(1.0f, 0.0f);
        #pragma unroll
        for (int j = 0; j < 5; j++) {
            int q   = 7 + j;
            int bit = (tid >> (4 - j)) & 1;
            v = bit ? make_float2(v.y * ssn[q], -v.x * ssn[q])  // v * (-i sin)
                    : make_float2(v.x * sc[q],   v.y * sc[q]);  // v * cos
        }
        sL[tid] = v;
    }
    __syncthreads();

    // ---- stage 2: direct product-state init (RX embedding on |0..0>) ----
    {
        float2 h = make_float2(1.0f, 0.0f);
        #pragma unroll
        for (int j = 0; j < 7; j++) {
            int bit = (tid >> (6 - j)) & 1;
            h = bit ? make_float2(h.y * ssn[j], -h.x * ssn[j])
                    : make_float2(h.x * sc[j],   h.y * sc[j]);
        }
        #pragma unroll
        for (int lo = 0; lo < 32; lo++) {
            unsigned p = tid * APT + lo;
            sAmp[SWZ(p)] = cmul(h, sL[lo]);
        }
    }
    __syncthreads();

    // ---- stage 3: variational layers; 4 gates fused, CNOTs folded into masks ----
    // Invariant entering layer l: sPhys[p] = sLogical[A p], A = T^l, B = A^-1.
    // Key structural facts: leading bit of colB[q] is always q, so the pivot
    // block for pass qp is exactly bits [8-qp .. 11-qp]; and rowA[j].colB[k]=delta_jk
    // so coset parities are independent.
    for (int l = 0; l < NLAYERS; l++) {
        #pragma unroll
        for (int qp = 0; qp < NQ; qp += 4) {
            const int jA = 11 - qp;
            const int pb = 8 - qp;                 // pivot block low bit: 8,4,0
            const unsigned mA = sColB[jA],     mB = sColB[jA - 1];
            const unsigned mC = sColB[jA - 2], mD = sColB[jA - 3];
            const unsigned rA = sRowA[jA],     rB = sRowA[jA - 1];
            const unsigned rC = sRowA[jA - 2], rD = sRowA[jA - 3];
            // swizzled pair masks (SWZ is linear)
            const unsigned wA = SWZ(mA), wB = SWZ(mB);
            const unsigned wC = SWZ(mC), wD = SWZ(mD);
            const unsigned lomask = (pb > 0) ? ((1u << pb) - 1u) : 0u;

            const int gi = (l * NQ + qp) * 4;

            #pragma unroll
            for (int it = 0; it < DIM / 16 / THREADS; it++) {  // 2 groups/thread
                unsigned g   = tid + it * THREADS;             // 8-bit coset id
                unsigned rep = ((g >> pb) << (pb + 4)) | (g & lomask);
                const unsigned sb = SWZ(rep);
                // coset parities (independent): logical bit of member k is k_g ^ c_g
                const unsigned cA = __popc(rA & rep) & 1u;
                const unsigned cB = __popc(rB & rep) & 1u;
                const unsigned cC = __popc(rC & rep) & 1u;
                const unsigned cD = __popc(rD & rep) & 1u;

                float2 v[16];
                #pragma unroll
                for (int k = 0; k < 16; k++) {
                    unsigned off = ((k & 8) ? wA : 0u) ^ ((k & 4) ? wB : 0u)
                                 ^ ((k & 2) ? wC : 0u) ^ ((k & 1) ? wD : 0u);
                    v[k] = sAmp[sb ^ off];
                }
                {   // gate A (group bit 3); coefficients swapped if cA (G -> XGX)
                    const float2 G00 = sGate[gi + 0], G01 = sGate[gi + 1];
                    const float2 G10 = sGate[gi + 2], G11 = sGate[gi + 3];
                    const float2 a00 = cA ? G11 : G00, a01 = cA ? G10 : G01;
                    const float2 a10 = cA ? G01 : G10, a11 = cA ? G00 : G11;
                    #pragma unroll
                    for (int k = 0; k < 8; k++) {
                        float2 v0 = v[k], v1 = v[k + 8];
                        v[k]     = cfma(a00, v0, cmul(a01, v1));
                        v[k + 8] = cfma(a10, v0, cmul(a11, v1));
                    }
                }
                {   // gate B (group bit 2)
                    const float2 G00 = sGate[gi + 4], G01 = sGate[gi + 5];
                    const float2 G10 = sGate[gi + 6], G11 = sGate[gi + 7];
                    const float2 a00 = cB ? G11 : G00, a01 = cB ? G10 : G01;
                    const float2 a10 = cB ? G01 : G10, a11 = cB ? G00 : G11;
                    #pragma unroll
                    for (int h = 0; h < 16; h += 8)
                        #pragma unroll
                        for (int k = 0; k < 4; k++) {
                            float2 v0 = v[h + k], v1 = v[h + k + 4];
                            v[h + k]     = cfma(a00, v0, cmul(a01, v1));
                            v[h + k + 4] = cfma(a10, v0, cmul(a11, v1));
                        }
                }
                {   // gate C (group bit 1)
                    const float2 G00 = sGate[gi + 8],  G01 = sGate[gi + 9];
                    const float2 G10 = sGate[gi + 10], G11 = sGate[gi + 11];
                    const float2 a00 = cC ? G11 : G00, a01 = cC ? G10 : G01;
                    const float2 a10 = cC ? G01 : G10, a11 = cC ? G00 : G11;
                    #pragma unroll
                    for (int h = 0; h < 16; h += 4)
                        #pragma unroll
                        for (int k = 0; k < 2; k++) {
                            float2 v0 = v[h + k], v1 = v[h + k + 2];
                            v[h + k]     = cfma(a00, v0, cmul(a01, v1));
                            v[h + k + 2] = cfma(a10, v0, cmul(a11, v1));
                        }
                }
                {   // gate D (group bit 0)
                    const float2 G00 = sGate[gi + 12], G01 = sGate[gi + 13];
                    const float2 G10 = sGate[gi + 14], G11 = sGate[gi + 15];
                    const float2 a00 = cD ? G11 : G00, a01 = cD ? G10 : G01;
                    const float2 a10 = cD ? G01 : G10, a11 = cD ? G00 : G11;
                    #pragma unroll
                    for (int k = 0; k < 16; k += 2) {
                        float2 v0 = v[k], v1 = v[k + 1];
                        v[k]     = cfma(a00, v0, cmul(a01, v1));
                        v[k + 1] = cfma(a10, v0, cmul(a11, v1));
                    }
                }
                #pragma unroll
                for (int k = 0; k < 16; k++) {
                    unsigned off = ((k & 8) ? wA : 0u) ^ ((k & 4) ? wB : 0u)
                                 ^ ((k & 2) ? wC : 0u) ^ ((k & 1) ? wD : 0u);
                    sAmp[sb ^ off] = v[k];
                }
            }
            __syncthreads();
        }
        // CNOT chain as matrix update:  A <- T*A ;  B <- B*T^-1
        if (tid == 0) {
            unsigned acc = 0;
            #pragma unroll
            for (int j = NQ - 1; j >= 0; j--) { acc ^= sRowA[j]; sRowA[j] = acc; }
            #pragma unroll
            for (int q = NQ - 1; q >= 1; q--) sColB[q] ^= sColB[q - 1];
        }
        __syncthreads();
    }

    // ---- stage 4: probabilities -> <Z_q> with permuted sign masks ----
    unsigned rq[NQ];
    #pragma unroll
    for (int q = 0; q < NQ; q++) rq[q] = sRowA[11 - q];

    float e[NQ];
    #pragma unroll
    for (int q = 0; q < NQ; q++) e[q] = 0.0f;

    #pragma unroll
    for (int lo = 0; lo < APT; lo++) {
        unsigned p = tid + lo * THREADS;   // lane-contiguous -> conflict-free under SWZ
        float2 a = sAmp[SWZ(p)];
        float pr = fmaf(a.x, a.x, a.y * a.y);
        #pragma unroll
        for (int q = 0; q < NQ; q++)
            e[q] += (__popc(rq[q] & p) & 1) ? -pr : pr;
    }

    #pragma unroll
    for (int q = 0; q < NQ; q++) {
        float v = e[q];
        #pragma unroll
        for (int off = 16; off > 0; off >>= 1)
            v += __shfl_down_sync(0xffffffffu, v, off);
        if ((tid & 31) == 0) atomicAdd(&sExp[q], v);
    }
    __syncthreads();

    // ---- stage 5: readout mitigation, closed form ----
    // M = J - I => M^-1 = J/(n-1) - I ; out_q = (E+12)/11 - e_q - 2
    if (tid < NQ) {
        float E = 0.0f;
        #pragma unroll
        for (int q = 0; q < NQ; q++) E += sExp[q];
        out[b * NQ + tid] = (E + 12.0f) * (1.0f / 11.0f) - sExp[tid] - 2.0f;
    }
}

extern "C" void kernel_launch(void* const* d_in, const int* in_sizes, int n_in,
                              void* d_out, int out_size) {
    const float* x      = (const float*)d_in[0];
    const float* params = (const float*)d_in[1];
    if (n_in >= 2 && in_sizes[0] == NLAYERS * NQ * 3) {
        x      = (const float*)d_in[1];
        params = (const float*)d_in[0];
    }
    cudaFuncSetAttribute(qsim_kernel,
                         cudaFuncAttributePreferredSharedMemoryCarveout, 100);
    int nblk = out_size / NQ;   // 768
    qsim_kernel<<<nblk, THREADS>>>(x, params, (float*)d_out);
}

// round 7
// speedup vs baseline: 1.2816x; 1.2616x over previous
#include <cuda_runtime.h>

#define NQ       12
#define DIM      4096            // 2^12
#define NLAYERS  6
#define NGATES   (NLAYERS * NQ)  // 72
#define THREADS  128
#define APT      (DIM / THREADS) // 32 amplitudes per thread

typedef unsigned long long ull;

// Bank-conflict-avoiding layout: amplitude p lives at sAmp[SWZ(p)].
// GF(2)-linear and invertible: SWZ(a^b) = SWZ(a)^SWZ(b).
#define SWZ(p) ((p) ^ (((p) >> 4) & 0xFu))

// GF(2) matrices of the CNOT-chain map, precomputed per layer.
// T: (Ta)_j = XOR_{k>=j} a_k.  cROWA[l][j] = row j of T^l ; cCOLB[l][q] = col q of T^-l.
// Invariants verified: rowA.colB = I; leading bit of cCOLB[l][q] is q (pivot structure).
__constant__ unsigned cROWA[NLAYERS + 1][NQ] = {
    {0x001,0x002,0x004,0x008,0x010,0x020,0x040,0x080,0x100,0x200,0x400,0x800},
    {0xFFF,0xFFE,0xFFC,0xFF8,0xFF0,0xFE0,0xFC0,0xF80,0xF00,0xE00,0xC00,0x800},
    {0x555,0xAAA,0x554,0xAA8,0x550,0xAA0,0x540,0xA80,0x500,0xA00,0x400,0x800},
    {0x333,0x666,0xCCC,0x998,0x330,0x660,0xCC0,0x980,0x300,0x600,0xC00,0x800},
    {0x111,0x222,0x444,0x888,0x110,0x220,0x440,0x880,0x100,0x200,0x400,0x800},
    {0xF0F,0xE1E,0xC3C,0x878,0x0F0,0x1E0,0x3C0,0x780,0xF00,0xE00,0xC00,0x800},
    {0x505,0xA0A,0x414,0x828,0x050,0x0A0,0x140,0x280,0x500,0xA00,0x400,0x800},
};
__constant__ unsigned cCOLB[NLAYERS][NQ] = {
    {0x001,0x002,0x004,0x008,0x010,0x020,0x040,0x080,0x100,0x200,0x400,0x800},
    {0x001,0x003,0x006,0x00C,0x018,0x030,0x060,0x0C0,0x180,0x300,0x600,0xC00},
    {0x001,0x002,0x005,0x00A,0x014,0x028,0x050,0x0A0,0x140,0x280,0x500,0xA00},
    {0x001,0x003,0x007,0x00F,0x01E,0x03C,0x078,0x0F0,0x1E0,0x3C0,0x780,0xF00},
    {0x001,0x002,0x004,0x008,0x011,0x022,0x044,0x088,0x110,0x220,0x440,0x880},
    {0x001,0x003,0x006,0x00C,0x019,0x033,0x066,0x0CC,0x198,0x330,0x660,0xCC0},
};

// ---- packed f32x2 primitives (Blackwell FFMA2 path) ----
__device__ __forceinline__ ull f2mul(ull a, ull b) {
    ull d; asm("mul.rn.f32x2 %0, %1, %2;" : "=l"(d) : "l"(a), "l"(b)); return d;
}
__device__ __forceinline__ ull f2fma(ull a, ull b, ull c) {
    ull d; asm("fma.rn.f32x2 %0, %1, %2, %3;" : "=l"(d) : "l"(a), "l"(b), "l"(c)); return d;
}
__device__ __forceinline__ ull f2swap(ull v) {  // (re,im) -> (im,re)
    ull d;
    asm("{\n\t.reg .b32 lo, hi;\n\tmov.b64 {lo, hi}, %1;\n\tmov.b64 %0, {hi, lo};\n\t}"
        : "=l"(d) : "l"(v));
    return d;
}
__device__ __forceinline__ ull packf2(float lo, float hi) {
    return (ull)__float_as_uint(lo) | ((ull)__float_as_uint(hi) << 32);
}

// One complex 2x2 butterfly on packed amplitudes.
// Coefficient g=(gr,gi) is pre-split into rXX=(gr,gr) and iXX=(-gi,gi);
// g*v = rXX*v + iXX*swap(v) componentwise under f32x2.
__device__ __forceinline__ void bf(ull& x0, ull& x1,
                                   ull r00, ull i00, ull r01, ull i01,
                                   ull r10, ull i10, ull r11, ull i11) {
    ull s0 = f2swap(x0), s1 = f2swap(x1);
    ull o0 = f2mul(r00, x0);
    o0 = f2fma(i00, s0, o0);
    o0 = f2fma(r01, x1, o0);
    o0 = f2fma(i01, s1, o0);
    ull o1 = f2mul(r10, x0);
    o1 = f2fma(i10, s0, o1);
    o1 = f2fma(r11, x1, o1);
    o1 = f2fma(i11, s1, o1);
    x0 = o0; x1 = o1;
}

__global__ __launch_bounds__(THREADS, 6)
void qsim_kernel(const float* __restrict__ x,
                 const float* __restrict__ params,
                 float* __restrict__ out) {
    __shared__ ull    sAmp[DIM];            // 32 KB statevector, packed (re,im), swizzled
    __shared__ ull    sGateP[NGATES * 8];   // 4.5 KB: per gate 4 entries x (RR,II) packed
    __shared__ float  sc[NQ], ssn[NQ];      // cos(x/2), sin(x/2)
    __shared__ float2 sL[32];               // product table, qubits 7..11
    __shared__ float  sExp[NQ];             // <Z_q> accumulators

    float2* sAmpF = reinterpret_cast<float2*>(sAmp);

    const int tid = threadIdx.x;
    const int b   = blockIdx.x;

    // ---- stage 0: trig + packed gate coefficient table ----
    if (tid < NQ) {
        float xv = x[b * NQ + tid];
        sc[tid]   = cosf(0.5f * xv);
        ssn[tid]  = sinf(0.5f * xv);
        sExp[tid] = 0.0f;
    }
    if (tid < NGATES) {
        float phi = params[tid * 3 + 0];
        float th  = params[tid * 3 + 1];
        float om  = params[tid * 3 + 2];
        float ct = cosf(0.5f * th), st = sinf(0.5f * th);
        float aa = 0.5f * (phi + om), bb = 0.5f * (phi - om);
        float ca = cosf(aa), sa = sinf(aa);
        float cb = cosf(bb), sb = sinf(bb);
        // Rot = [[ep*ct, -em*st], [conj(em)*st, conj(ep)*ct]], ep=ca-i sa, em=cb+i sb
        float2 G00 = make_float2( ca * ct, -sa * ct);
        float2 G01 = make_float2(-cb * st, -sb * st);
        float2 G10 = make_float2( cb * st, -sb * st);
        float2 G11 = make_float2( ca * ct,  sa * ct);
        int base = tid * 8;
        sGateP[base + 0] = packf2(G00.x, G00.x); sGateP[base + 1] = packf2(-G00.y, G00.y);
        sGateP[base + 2] = packf2(G01.x, G01.x); sGateP[base + 3] = packf2(-G01.y, G01.y);
        sGateP[base + 4] = packf2(G10.x, G10.x); sGateP[base + 5] = packf2(-G10.y, G10.y);
        sGateP[base + 6] = packf2(G11.x, G11.x); sGateP[base + 7] = packf2(-G11.y, G11.y);
    }
    __syncthreads();

    // ---- stage 1: low-5-bit product table (qubits 7..11 <-> bits 4..0) ----
    if (tid < 32) {
        float2 v = make_float2(1.0f, 0.0f);
        #pragma unroll
        for (int j = 0; j < 5; j++) {
            int q   = 7 + j;
            int bit = (tid >> (4 - j)) & 1;
            v = bit ? make_float2(v.y * ssn[q], -v.x * ssn[q])  // v * (-i sin)
                    : make_float2(v.x * sc[q],   v.y * sc[q]);  // v * cos
        }
        sL[tid] = v;
    }
    __syncthreads();

    // ---- stage 2: direct product-state init (RX embedding on |0..0>) ----
    {
        float2 h = make_float2(1.0f, 0.0f);
        #pragma unroll
        for (int j = 0; j < 7; j++) {
            int bit = (tid >> (6 - j)) & 1;
            h = bit ? make_float2(h.y * ssn[j], -h.x * ssn[j])
                    : make_float2(h.x * sc[j],   h.y * sc[j]);
        }
        #pragma unroll
        for (int lo = 0; lo < 32; lo++) {
            unsigned p = tid * APT + lo;
            float2 g = sL[lo];
            float2 r = make_float2(fmaf(h.x, g.x, -h.y * g.y),
                                   fmaf(h.x, g.y,  h.y * g.x));
            sAmpF[SWZ(p)] = r;
        }
    }
    __syncthreads();

    // ---- stage 3: variational layers; 4 gates fused, CNOTs folded into masks ----
    // Invariant entering layer l: sPhys[p] = sLogical[(T^l) p].
    for (int l = 0; l < NLAYERS; l++) {
        #pragma unroll
        for (int qp = 0; qp < NQ; qp += 4) {
            const int jA = 11 - qp;
            const int pb = 8 - qp;                 // pivot block low bit: 8,4,0
            const unsigned mA = cCOLB[l][jA],     mB = cCOLB[l][jA - 1];
            const unsigned mC = cCOLB[l][jA - 2], mD = cCOLB[l][jA - 3];
            const unsigned rA = cROWA[l][jA],     rB = cROWA[l][jA - 1];
            const unsigned rC = cROWA[l][jA - 2], rD = cROWA[l][jA - 3];
            const unsigned wA = SWZ(mA), wB = SWZ(mB);
            const unsigned wC = SWZ(mC), wD = SWZ(mD);
            const unsigned lomask = (pb > 0) ? ((1u << pb) - 1u) : 0u;
            const int g8 = (l * NQ + qp) * 8;      // packed-coeff base (gate A)

            #pragma unroll
            for (int it = 0; it < DIM / 16 / THREADS; it++) {  // 2 groups/thread
                unsigned g   = tid + it * THREADS;             // 8-bit coset id
                unsigned rep = ((g >> pb) << (pb + 4)) | (g & lomask);
                const unsigned sb = SWZ(rep);
                // coset parities: orientation selector per gate (independent)
                const unsigned cA = __popc(rA & rep) & 1u;
                const unsigned cB = __popc(rB & rep) & 1u;
                const unsigned cC = __popc(rC & rep) & 1u;
                const unsigned cD = __popc(rD & rep) & 1u;

                ull v[16];
                #pragma unroll
                for (int k = 0; k < 16; k++) {
                    unsigned off = ((k & 8) ? wA : 0u) ^ ((k & 4) ? wB : 0u)
                                 ^ ((k & 2) ? wC : 0u) ^ ((k & 1) ? wD : 0u);
                    v[k] = sAmp[sb ^ off];
                }
                {   // gate A (group bit 3); c=1 -> XGX = entry reversal = idx XOR 6
                    const unsigned co = cA * 6u;
                    ull r00 = sGateP[g8 + (0u ^ co)],      i00 = sGateP[g8 + (0u ^ co) + 1];
                    ull r01 = sGateP[g8 + (2u ^ co)],      i01 = sGateP[g8 + (2u ^ co) + 1];
                    ull r10 = sGateP[g8 + (4u ^ co)],      i10 = sGateP[g8 + (4u ^ co) + 1];
                    ull r11 = sGateP[g8 + (6u ^ co)],      i11 = sGateP[g8 + (6u ^ co) + 1];
                    #pragma unroll
                    for (int k = 0; k < 8; k++)
                        bf(v[k], v[k + 8], r00, i00, r01, i01, r10, i10, r11, i11);
                }
                {   // gate B (group bit 2)
                    const unsigned co = cB * 6u;
                    const int gb = g8 + 8;
                    ull r00 = sGateP[gb + (0u ^ co)],      i00 = sGateP[gb + (0u ^ co) + 1];
                    ull r01 = sGateP[gb + (2u ^ co)],      i01 = sGateP[gb + (2u ^ co) + 1];
                    ull r10 = sGateP[gb + (4u ^ co)],      i10 = sGateP[gb + (4u ^ co) + 1];
                    ull r11 = sGateP[gb + (6u ^ co)],      i11 = sGateP[gb + (6u ^ co) + 1];
                    #pragma unroll
                    for (int h = 0; h < 16; h += 8)
                        #pragma unroll
                        for (int k = 0; k < 4; k++)
                            bf(v[h + k], v[h + k + 4], r00, i00, r01, i01, r10, i10, r11, i11);
                }
                {   // gate C (group bit 1)
                    const unsigned co = cC * 6u;
                    const int gb = g8 + 16;
                    ull r00 = sGateP[gb + (0u ^ co)],      i00 = sGateP[gb + (0u ^ co) + 1];
                    ull r01 = sGateP[gb + (2u ^ co)],      i01 = sGateP[gb + (2u ^ co) + 1];
                    ull r10 = sGateP[gb + (4u ^ co)],      i10 = sGateP[gb + (4u ^ co) + 1];
                    ull r11 = sGateP[gb + (6u ^ co)],      i11 = sGateP[gb + (6u ^ co) + 1];
                    #pragma unroll
                    for (int h = 0; h < 16; h += 4)
                        #pragma unroll
                        for (int k = 0; k < 2; k++)
                            bf(v[h + k], v[h + k + 2], r00, i00, r01, i01, r10, i10, r11, i11);
                }
                {   // gate D (group bit 0)
                    const unsigned co = cD * 6u;
                    const int gb = g8 + 24;
                    ull r00 = sGateP[gb + (0u ^ co)],      i00 = sGateP[gb + (0u ^ co) + 1];
                    ull r01 = sGateP[gb + (2u ^ co)],      i01 = sGateP[gb + (2u ^ co) + 1];
                    ull r10 = sGateP[gb + (4u ^ co)],      i10 = sGateP[gb + (4u ^ co) + 1];
                    ull r11 = sGateP[gb + (6u ^ co)],      i11 = sGateP[gb + (6u ^ co) + 1];
                    #pragma unroll
                    for (int k = 0; k < 16; k += 2)
                        bf(v[k], v[k + 1], r00, i00, r01, i01, r10, i10, r11, i11);
                }
                #pragma unroll
                for (int k = 0; k < 16; k++) {
                    unsigned off = ((k & 8) ? wA : 0u) ^ ((k & 4) ? wB : 0u)
                                 ^ ((k & 2) ? wC : 0u) ^ ((k & 1) ? wD : 0u);
                    sAmp[sb ^ off] = v[k];
                }
            }
            __syncthreads();
        }
        // no per-layer matrix update: masks are compile-time (cROWA/cCOLB)
    }

    // ---- stage 4: probabilities -> <Z_q> with permuted sign masks ----
    // sign of Z_q at physical p = (-1)^parity(cROWA[6][11-q] & p)
    float e[NQ];
    #pragma unroll
    for (int q = 0; q < NQ; q++) e[q] = 0.0f;

    #pragma unroll
    for (int lo = 0; lo < APT; lo++) {
        unsigned p = tid + lo * THREADS;
        float2 a = sAmpF[SWZ(p)];
        float pr = fmaf(a.x, a.x, a.y * a.y);
        #pragma unroll
        for (int q = 0; q < NQ; q++)
            e[q] += (__popc(cROWA[NLAYERS][11 - q] & p) & 1) ? -pr : pr;
    }

    #pragma unroll
    for (int q = 0; q < NQ; q++) {
        float v = e[q];
        #pragma unroll
        for (int off = 16; off > 0; off >>= 1)
            v += __shfl_down_sync(0xffffffffu, v, off);
        if ((tid & 31) == 0) atomicAdd(&sExp[q], v);
    }
    __syncthreads();

    // ---- stage 5: readout mitigation, closed form ----
    // M = J - I => M^-1 = J/(n-1) - I ; out_q = (E+12)/11 - e_q - 2
    if (tid < NQ) {
        float E = 0.0f;
        #pragma unroll
        for (int q = 0; q < NQ; q++) E += sExp[q];
        out[b * NQ + tid] = (E + 12.0f) * (1.0f / 11.0f) - sExp[tid] - 2.0f;
    }
}

extern "C" void kernel_launch(void* const* d_in, const int* in_sizes, int n_in,
                              void* d_out, int out_size) {
    const float* x      = (const float*)d_in[0];
    const float* params = (const float*)d_in[1];
    if (n_in >= 2 && in_sizes[0] == NLAYERS * NQ * 3) {
        x      = (const float*)d_in[1];
        params = (const float*)d_in[0];
    }
    cudaFuncSetAttribute(qsim_kernel,
                         cudaFuncAttributePreferredSharedMemoryCarveout, 100);
    int nblk = out_size / NQ;   // 768
    qsim_kernel<<<nblk, THREADS>>>(x, params, (float*)d_out);
}